// round 1
// baseline (speedup 1.0000x reference)
#include <cuda_runtime.h>
#include <math.h>

#define BB 2048
#define CC 3
#define TT 300
#define JJ 25
#define TJ (TT * JJ)      // 7500 elements per (b,c) slice
#define NBLK (BB * CC)    // 6144 blocks
#define NTHREADS 256

// Global accumulators (allocation-free scratch).
__device__ double g_rec;
__device__ double g_smooth;

__global__ void zero_acc_kernel() {
    g_rec = 0.0;
    g_smooth = 0.0;
}

__global__ void __launch_bounds__(NTHREADS)
loss_kernel(const float* __restrict__ x, const float* __restrict__ tg) {
    const int bc = blockIdx.x;
    const float4* __restrict__ x4 = (const float4*)(x  + (size_t)bc * TJ);
    const float4* __restrict__ t4 = (const float4*)(tg + (size_t)bc * TJ);

    __shared__ float sd[JJ];              // per-joint (sx - st) accumulator
    __shared__ float swarp[NTHREADS / 32];

    if (threadIdx.x < JJ) sd[threadIdx.x] = 0.0f;
    __syncthreads();

    float rec = 0.0f;

    // TJ = 7500, divisible by 4 -> 1875 float4 per tensor per block.
    #pragma unroll 2
    for (int i = threadIdx.x; i < TJ / 4; i += NTHREADS) {
        float4 xv = x4[i];
        float4 tv = t4[i];
        const float xa[4] = {xv.x, xv.y, xv.z, xv.w};
        const float ta[4] = {tv.x, tv.y, tv.z, tv.w};
        const int base = i * 4;
        #pragma unroll
        for (int k = 0; k < 4; k++) {
            const float xf = xa[k];
            const float tf = ta[k];
            const float d = xf - tf;
            rec = fmaf(d, d, rec);

            const int idx = base + k;
            const int t_idx = idx / JJ;          // const divisor -> mul/shift
            const int j = idx - t_idx * JJ;

            // Per-element contribution to (sx[j] - st[j]):
            //   element at frame t contributes +x to sx if t < T-1,
            //   and -x^2 to sx if t > 0.  (Same for target, negated.)
            float contrib = 0.0f;
            if (t_idx < TT - 1) contrib += (xf - tf);
            if (t_idx > 0)      contrib -= (xf * xf - tf * tf);
            atomicAdd(&sd[j], contrib);
        }
    }

    // Block reduction for rec.
    #pragma unroll
    for (int o = 16; o > 0; o >>= 1)
        rec += __shfl_down_sync(0xffffffffu, rec, o);
    if ((threadIdx.x & 31) == 0) swarp[threadIdx.x >> 5] = rec;
    __syncthreads();

    if (threadIdx.x == 0) {
        float rtot = 0.0f;
        #pragma unroll
        for (int w = 0; w < NTHREADS / 32; w++) rtot += swarp[w];

        float total = 0.0f;
        #pragma unroll
        for (int j = 0; j < JJ - 1; j++) total += fabsf(sd[j]);

        atomicAdd(&g_rec, (double)rtot);
        atomicAdd(&g_smooth, sqrt((double)total) / (double)(JJ * TT));
    }
}

__global__ void finalize_kernel(float* __restrict__ out) {
    const double rec_mean    = g_rec    / ((double)BB * CC * TT * JJ);
    const double smooth_mean = g_smooth / ((double)BB * CC);
    out[0] = (float)(2.0 * rec_mean + 3.0 * smooth_mean);
}

extern "C" void kernel_launch(void* const* d_in, const int* in_sizes, int n_in,
                              void* d_out, int out_size) {
    const float* x  = (const float*)d_in[0];
    const float* tg = (const float*)d_in[1];
    float* out = (float*)d_out;

    zero_acc_kernel<<<1, 1>>>();
    loss_kernel<<<NBLK, NTHREADS>>>(x, tg);
    finalize_kernel<<<1, 1>>>(out);
}

// round 2
// speedup vs baseline: 1.8654x; 1.8654x over previous
#include <cuda_runtime.h>
#include <math.h>

#define BB 2048
#define CC 3
#define TT 300
#define JJ 25
#define TJ (TT * JJ)            // 7500 elements per (b,c) slice
#define NSLICE (BB * CC)        // 6144 slices
#define WPB 8                   // warps per block (1 warp = 1 slice)
#define NBLK (NSLICE / WPB)     // 768 blocks
#define NTHREADS (WPB * 32)

// Global accumulators (allocation-free scratch).
__device__ double g_rec;
__device__ double g_smooth;

__global__ void zero_acc_kernel() {
    g_rec = 0.0;
    g_smooth = 0.0;
}

__global__ void __launch_bounds__(NTHREADS)
loss_kernel(const float* __restrict__ x, const float* __restrict__ tg) {
    const int warp = threadIdx.x >> 5;
    const int lane = threadIdx.x & 31;
    const int slice = blockIdx.x * WPB + warp;          // < 6144

    const float* __restrict__ xs = x  + (size_t)slice * TJ;
    const float* __restrict__ ts = tg + (size_t)slice * TJ;

    const bool active = (lane < JJ);

    float accd = 0.0f;   // (sx - st) for joint j = lane
    float rec  = 0.0f;   // sum of (x - t)^2 over this lane's elements

    #pragma unroll 4
    for (int t = 0; t < TT; t++) {
        float xf = 0.0f, tf = 0.0f;
        if (active) {
            xf = __ldg(xs + t * JJ + lane);
            tf = __ldg(ts + t * JJ + lane);
        }
        const float d = xf - tf;
        rec = fmaf(d, d, rec);

        // element at frame t contributes +x to sx if t < T-1,
        // and -x^2 to sx if t > 0 (targets negated).
        float c = (t < TT - 1) ? d : 0.0f;
        if (t > 0) c -= (xf * xf - tf * tf);
        accd += c;
    }

    // Warp reduction: smooth uses joints 0..J-2 only (lanes 0..23).
    float av = (lane < JJ - 1) ? fabsf(accd) : 0.0f;
    #pragma unroll
    for (int o = 16; o > 0; o >>= 1) {
        av  += __shfl_xor_sync(0xffffffffu, av,  o);
        rec += __shfl_xor_sync(0xffffffffu, rec, o);
    }

    __shared__ double s_rec[WPB];
    __shared__ double s_sm[WPB];
    if (lane == 0) {
        s_rec[warp] = (double)rec;
        s_sm[warp]  = sqrt((double)av) / (double)TJ;
    }
    __syncthreads();

    if (threadIdx.x == 0) {
        double rtot = 0.0, stot = 0.0;
        #pragma unroll
        for (int w = 0; w < WPB; w++) { rtot += s_rec[w]; stot += s_sm[w]; }
        atomicAdd(&g_rec, rtot);
        atomicAdd(&g_smooth, stot);
    }
}

__global__ void finalize_kernel(float* __restrict__ out) {
    const double rec_mean    = g_rec    / ((double)BB * CC * TT * JJ);
    const double smooth_mean = g_smooth / ((double)BB * CC);
    out[0] = (float)(2.0 * rec_mean + 3.0 * smooth_mean);
}

extern "C" void kernel_launch(void* const* d_in, const int* in_sizes, int n_in,
                              void* d_out, int out_size) {
    const float* x  = (const float*)d_in[0];
    const float* tg = (const float*)d_in[1];
    float* out = (float*)d_out;

    zero_acc_kernel<<<1, 1>>>();
    loss_kernel<<<NBLK, NTHREADS>>>(x, tg);
    finalize_kernel<<<1, 1>>>(out);
}